// round 4
// baseline (speedup 1.0000x reference)
#include <cuda_runtime.h>

// ---------------------------------------------------------------------------
// EventGRUBayes — register-stationary-weight persistent solver.
// Shape: B=1024, H=64, IN=8, OH=128, OUT=2; 400 events (event k at step k),
// 500 grid steps. 128 blocks x 256 threads; block owns 8 samples.
// Each thread holds 2 full weight rows (+Wih row, +ghh quarter) in registers;
// h is broadcast-read from SMEM; math uses packed fma.rn.f32x2.
// ---------------------------------------------------------------------------

#define B_     1024
#define NEV    400
#define NSTEPS 500
#define OPE_   256
#define TOT_   (NEV * OPE_)
#define DT_    0.01f

typedef unsigned long long ull;

__device__ int g_winner[NEV * B_];   // winner[step][sample] = max obs idx, -1 none

__global__ void winner_init_k() {
    int i = blockIdx.x * blockDim.x + threadIdx.x;
    if (i < NEV * B_) g_winner[i] = -1;
}
__global__ void winner_scatter_k(const int* __restrict__ sid) {
    int j = blockIdx.x * blockDim.x + threadIdx.x;
    if (j < TOT_) atomicMax(&g_winner[(j >> 8) * B_ + sid[j]], j);
}

__device__ __forceinline__ float sigm(float x) {
    return __fdividef(1.f, 1.f + __expf(-x));
}
__device__ __forceinline__ float tanh_f(float x) {
    float xc = fminf(fmaxf(x, -15.f), 15.f);
    float e  = __expf(-2.f * xc);
    return __fdividef(1.f - e, 1.f + e);
}

// packed 2xfp32 fma: d = a*b + c  (per-half)
#define FMA2(d, a, b, c) \
    asm("fma.rn.f32x2 %0, %1, %2, %3;" : "=l"(d) : "l"(a), "l"(b), "l"(c))

__device__ __forceinline__ float hadd2(ull v) {
    unsigned lo, hi;
    asm("mov.b64 {%0, %1}, %2;" : "=r"(lo), "=r"(hi) : "l"(v));
    return __uint_as_float(lo) + __uint_as_float(hi);
}

// ---- static shared state (≈32 KB) ----
__shared__ __align__(16) float sh_h  [8][64];
__shared__ __align__(16) float sh_rh [8][64];
__shared__ __align__(16) float sh_evr[8][64];
__shared__ __align__(16) float sh_evz[8][64];
__shared__ __align__(16) float sh_eva[8][64];
__shared__ __align__(16) float sh_evc[8][64];
__shared__ __align__(16) float sh_part[8][320];   // [s][j*5+q]
__shared__ __align__(16) float sh_dd [8][136];    // head hidden, padded row
__shared__ __align__(16) float sh_xv [2][8][8];   // prefetched X rows
__shared__ __align__(16) float sh_w2 [256];
__shared__ __align__(16) float sh_ob1[128];
__shared__ __align__(16) float sh_gxb[192];
__shared__ __align__(16) float sh_bih[192];
__shared__ __align__(16) float sh_bhh[192];
__shared__            float sh_b2 [2];
__shared__            int   sh_win[2][8];

__global__ __launch_bounds__(256, 1)
void ev_gru_main(
    const float* __restrict__ X,
    const float* __restrict__ covs,
    const float* __restrict__ cW1, const float* __restrict__ cb1,
    const float* __restrict__ cW2, const float* __restrict__ cb2,
    const float* __restrict__ gWih, const float* __restrict__ gWhh,
    const float* __restrict__ gbih, const float* __restrict__ gbhh,
    const float* __restrict__ gxb,
    const float* __restrict__ ghrW, const float* __restrict__ ghzW,
    const float* __restrict__ ghhW,
    const float* __restrict__ oW1,  const float* __restrict__ ob1,
    const float* __restrict__ oW2,  const float* __restrict__ ob2,
    float* __restrict__ out)
{
    const int tid = threadIdx.x;
    const int blk = blockIdx.x;

    // ---- stage small vectors into SMEM ----
    if (tid < 192) {
        sh_gxb[tid] = gxb[tid];
        sh_bih[tid] = gbih[tid];
        sh_bhh[tid] = gbhh[tid];
    }
    if (tid < 128) sh_ob1[tid] = ob1[tid];
    sh_w2[tid] = oW2[tid];
    if (tid < 2) sh_b2[tid] = ob2[tid];

    // ---- register-stationary weights ----
    // pass1 row: t<64 -> ghr[t]; t<128 -> ghz[t-64]; else W1[t-128]
    ull wp1[32];
    {
        const float* src = (tid < 64)  ? ghrW + tid * 64
                         : (tid < 128) ? ghzW + (tid - 64) * 64
                                       : oW1  + (tid - 128) * 64;
        const ulonglong2* p = reinterpret_cast<const ulonglong2*>(src);
        #pragma unroll
        for (int i = 0; i < 16; i++) { ulonglong2 v = p[i]; wp1[2*i] = v.x; wp1[2*i+1] = v.y; }
    }
    // ghh quarter: row j = tid&63, chunk q = tid>>6 (16 floats)
    ull wq[8];
    {
        const float* src = ghhW + (tid & 63) * 64 + (tid >> 6) * 16;
        const ulonglong2* p = reinterpret_cast<const ulonglong2*>(src);
        #pragma unroll
        for (int i = 0; i < 4; i++) { ulonglong2 v = p[i]; wq[2*i] = v.x; wq[2*i+1] = v.y; }
    }
    // event rows (threads 64..255): Whh row g (64f) + Wih row g (8f), g = tid-64
    ull we[32], wx[4];
    if (tid >= 64) {
        const int g = tid - 64;
        const ulonglong2* p  = reinterpret_cast<const ulonglong2*>(gWhh + g * 64);
        #pragma unroll
        for (int i = 0; i < 16; i++) { ulonglong2 v = p[i]; we[2*i] = v.x; we[2*i+1] = v.y; }
        const ulonglong2* px = reinterpret_cast<const ulonglong2*>(gWih + g * 8);
        ulonglong2 v0 = px[0], v1 = px[1];
        wx[0] = v0.x; wx[1] = v0.y; wx[2] = v1.x; wx[3] = v1.y;
    }

    // ---- h0 init: warp s handles sample s ----
    {
        const int s = tid >> 5, lane = tid & 31, o2 = lane + 32;
        const int b = blk * 8 + s;
        float t1 = __ldg(cb1 + lane), t2 = __ldg(cb1 + o2);
        #pragma unroll
        for (int k = 0; k < 16; k++) {
            float cv = __ldg(covs + b * 16 + k);
            t1 = fmaf(cv, __ldg(cW1 + lane * 16 + k), t1);
            t2 = fmaf(cv, __ldg(cW1 + o2 * 16 + k),   t2);
        }
        sh_rh[s][lane] = fmaxf(t1, 0.f); sh_rh[s][o2] = fmaxf(t2, 0.f);
        __syncwarp();
        float a1 = __ldg(cb2 + lane), a2 = __ldg(cb2 + o2);
        #pragma unroll 8
        for (int c = 0; c < 64; c++) {
            float tv = sh_rh[s][c];
            a1 = fmaf(tv, __ldg(cW2 + lane * 64 + c), a1);
            a2 = fmaf(tv, __ldg(cW2 + o2 * 64 + c),   a2);
        }
        __syncwarp();
        sh_h[s][lane] = tanh_f(a1); sh_h[s][o2] = tanh_f(a2);
    }
    // prefetch winners/X for t=0
    if (tid < 8) {
        int w = g_winner[blk * 8 + tid];
        sh_win[0][tid] = w;
        if (w >= 0) {
            const float4* xp = reinterpret_cast<const float4*>(X + (size_t)w * 8);
            float4 xa = __ldg(xp), xb = __ldg(xp + 1);
            float4* dst = reinterpret_cast<float4*>(sh_xv[0][tid]);
            dst[0] = xa; dst[1] = xb;
        }
    }
    __syncthreads();

    // ---- role-based scalar biases (read once) ----
    const int g = tid - 64;
    float xr = 0.f, xz = 0.f, xh = 0.f, ebrz = 0.f, ena = 0.f, enc = 0.f;
    if (tid < 64)                  xr = sh_gxb[tid];
    else if (tid < 128)          { xz = sh_gxb[tid]; xh = sh_gxb[tid + 64]; }
    if (tid >= 64 && tid < 192)    ebrz = sh_bih[g] + sh_bhh[g];
    if (tid >= 192)              { ena = sh_bih[g]; enc = sh_bhh[g]; }
    float w1b = (tid >= 128) ? sh_ob1[tid - 128] : 0.f;

    float zreg[8];

    // ================= main time loop =================
    for (int t = 0; ; t++) {
        const int pb = t & 1;

        // ---- EVENT (GRU-Bayes, computed from pre-update h; last-dup wins) ----
        bool anyev = false;
        if (t < NEV) {
            #pragma unroll
            for (int s = 0; s < 8; s++) anyev |= (sh_win[pb][s] >= 0);
        }
        if (anyev) {
            if (tid >= 64) {
                #pragma unroll
                for (int s = 0; s < 8; s++) {
                    if (sh_win[pb][s] < 0) continue;
                    ull a0 = 0, a1 = 0;
                    const ulonglong2* hp = reinterpret_cast<const ulonglong2*>(sh_h[s]);
                    #pragma unroll
                    for (int i = 0; i < 16; i++) {
                        ulonglong2 hv = hp[i];
                        FMA2(a0, we[2*i],   hv.x, a0);
                        FMA2(a1, we[2*i+1], hv.y, a1);
                    }
                    float gh = hadd2(a0) + hadd2(a1);
                    ull b0 = 0;
                    const ulonglong2* xp = reinterpret_cast<const ulonglong2*>(sh_xv[pb][s]);
                    ulonglong2 x0 = xp[0], x1 = xp[1];
                    FMA2(b0, wx[0], x0.x, b0); FMA2(b0, wx[1], x0.y, b0);
                    FMA2(b0, wx[2], x1.x, b0); FMA2(b0, wx[3], x1.y, b0);
                    float gi = hadd2(b0);
                    if (g < 64)        sh_evr[s][g]       = sigm(gi + gh + ebrz);
                    else if (g < 128)  sh_evz[s][g - 64]  = sigm(gi + gh + ebrz);
                    else { sh_eva[s][g - 128] = gi + ena; sh_evc[s][g - 128] = gh + enc; }
                }
            }
            __syncthreads();
            if (tid >= 192) {
                const int j = g - 128;
                #pragma unroll
                for (int s = 0; s < 8; s++) {
                    if (sh_win[pb][s] < 0) continue;
                    float r = sh_evr[s][j], z = sh_evz[s][j];
                    float n = tanh_f(sh_eva[s][j] + r * sh_evc[s][j]);
                    float ho = sh_h[s][j];
                    sh_h[s][j] = fmaf(z, ho - n, n);       // (1-z)*n + z*h
                }
            }
            __syncthreads();
        }

        // ---- PASS1: every thread, its row vs all 8 samples ----
        float acc[8];
        #pragma unroll
        for (int s = 0; s < 8; s++) {
            ull a0 = 0, a1 = 0;
            const ulonglong2* hp = reinterpret_cast<const ulonglong2*>(sh_h[s]);
            #pragma unroll
            for (int i = 0; i < 16; i++) {
                ulonglong2 hv = hp[i];
                FMA2(a0, wp1[2*i],   hv.x, a0);
                FMA2(a1, wp1[2*i+1], hv.y, a1);
            }
            acc[s] = hadd2(a0) + hadd2(a1);
        }
        if (tid < 64) {
            #pragma unroll
            for (int s = 0; s < 8; s++) {
                float r = sigm(acc[s] + xr);
                sh_rh[s][tid] = r * sh_h[s][tid];
            }
        } else if (tid < 128) {
            #pragma unroll
            for (int s = 0; s < 8; s++) zreg[s] = sigm(acc[s] + xz);
        } else {
            const int j = tid - 128;
            #pragma unroll
            for (int s = 0; s < 8; s++) sh_dd[s][j] = fmaxf(acc[s] + w1b, 0.f);
        }
        __syncthreads();

        // ---- HEAD (threads 0..15): out[t][s][o] ----
        if (tid < 16) {
            const int s = tid >> 1, o = tid & 1;
            const float4* dp = reinterpret_cast<const float4*>(sh_dd[s]);
            const float4* wp = reinterpret_cast<const float4*>(sh_w2 + o * 128);
            float p = 0.f;
            #pragma unroll
            for (int i = 0; i < 32; i++) {
                float4 d = dp[i], w = wp[i];
                p = fmaf(d.x, w.x, p); p = fmaf(d.y, w.y, p);
                p = fmaf(d.z, w.z, p); p = fmaf(d.w, w.w, p);
            }
            out[(size_t)t * (B_ * 2) + (blk * 8 + s) * 2 + o] = p + sh_b2[o];
        }
        // ---- prefetch next winners (threads 16..23) ----
        if (t + 1 < NEV && tid >= 16 && tid < 24) {
            const int s = tid - 16;
            int w = g_winner[(t + 1) * B_ + blk * 8 + s];
            sh_win[pb ^ 1][s] = w;
            if (w >= 0) {
                const float4* xp = reinterpret_cast<const float4*>(X + (size_t)w * 8);
                float4 xa = __ldg(xp), xb = __ldg(xp + 1);
                float4* dst = reinterpret_cast<float4*>(sh_xv[pb ^ 1][s]);
                dst[0] = xa; dst[1] = xb;
            }
        }
        if (t == NSTEPS) break;

        // ---- PASS2: ghh quarter-dots on rh ----
        {
            const int j = tid & 63, q = tid >> 6;
            #pragma unroll
            for (int s = 0; s < 8; s++) {
                ull a0 = 0, a1 = 0;
                const ulonglong2* rp =
                    reinterpret_cast<const ulonglong2*>(sh_rh[s] + q * 16);
                #pragma unroll
                for (int i = 0; i < 4; i++) {
                    ulonglong2 rv = rp[i];
                    FMA2(a0, wq[2*i],   rv.x, a0);
                    FMA2(a1, wq[2*i+1], rv.y, a1);
                }
                sh_part[s][j * 5 + q] = hadd2(a0) + hadd2(a1);
            }
        }
        __syncthreads();

        // ---- Euler update by z-threads (64..127), j = tid-64 ----
        if (tid >= 64 && tid < 128) {
            const int j = tid - 64;
            #pragma unroll
            for (int s = 0; s < 8; s++) {
                float su = sh_part[s][j*5] + sh_part[s][j*5+1]
                         + sh_part[s][j*5+2] + sh_part[s][j*5+3];
                float u = tanh_f(xh + su);
                float hv = sh_h[s][j];
                sh_h[s][j] = fmaf(DT_ * (1.f - zreg[s]), u - hv, hv);
            }
        }
        __syncthreads();
    }
}

extern "C" void kernel_launch(void* const* d_in, const int* in_sizes, int n_in,
                              void* d_out, int out_size)
{
    (void)in_sizes; (void)n_in; (void)out_size;
    const float* X    = (const float*)d_in[2];
    const int*   sid  = (const int*)  d_in[3];
    const float* covs = (const float*)d_in[4];
    const float* cW1  = (const float*)d_in[6];
    const float* cb1  = (const float*)d_in[7];
    const float* cW2  = (const float*)d_in[8];
    const float* cb2  = (const float*)d_in[9];
    const float* gWih = (const float*)d_in[10];
    const float* gWhh = (const float*)d_in[11];
    const float* gbih = (const float*)d_in[12];
    const float* gbhh = (const float*)d_in[13];
    const float* gxb  = (const float*)d_in[15];
    const float* ghrW = (const float*)d_in[16];
    const float* ghzW = (const float*)d_in[17];
    const float* ghhW = (const float*)d_in[18];
    const float* oW1  = (const float*)d_in[19];
    const float* ob1  = (const float*)d_in[20];
    const float* oW2  = (const float*)d_in[21];
    const float* ob2  = (const float*)d_in[22];
    float* out = (float*)d_out;

    winner_init_k<<<(NEV * B_ + 255) / 256, 256>>>();
    winner_scatter_k<<<(TOT_ + 255) / 256, 256>>>(sid);

    ev_gru_main<<<B_ / 8, 256>>>(X, covs, cW1, cb1, cW2, cb2,
                                 gWih, gWhh, gbih, gbhh, gxb,
                                 ghrW, ghzW, ghhW, oW1, ob1, oW2, ob2, out);
}

// round 5
// speedup vs baseline: 1.6448x; 1.6448x over previous
#include <cuda_runtime.h>

// ---------------------------------------------------------------------------
// EventGRUBayes — warp-independent solver, 2 samples per warp (weight reuse),
// packed fma.rn.f32x2 math.
// Shape: B=1024, H=64, IN=8, OH=128, OUT=2; 400 events (event k fires at grid
// step k), 500 steps. 128 blocks x 128 threads; warp w owns samples 2w,2w+1.
// No block-wide syncs inside the time loop (warps fully independent).
// ---------------------------------------------------------------------------

#define B_     1024
#define NEV    400
#define NSTEPS 500
#define OPE_   256
#define TOT_   (NEV * OPE_)
#define DT_    0.01f

typedef unsigned long long ull;

// shared-memory float offsets (rows padded 64->68 / 8->12: conflict-free LDS.128)
#define OF_GHR 0
#define OF_GHZ (OF_GHR + 64*68)
#define OF_GHH (OF_GHZ + 64*68)
#define OF_WHH (OF_GHH + 64*68)
#define OF_W1  (OF_WHH + 192*68)
#define OF_WIH (OF_W1  + 128*68)
#define OF_BIH (OF_WIH + 192*12)
#define OF_BHH (OF_BIH + 192)
#define OF_GXB (OF_BHH + 192)
#define OF_OB1 (OF_GXB + 192)
#define OF_W2  (OF_OB1 + 128)
#define OF_OB2 (OF_W2  + 256)
#define OF_HS  (OF_OB2 + 4)
#define OF_RS  (OF_HS + 8*64)
#define SMEM_FLOATS (OF_RS + 8*64)

__device__ int g_winner[NEV * B_];   // winner[step][sample] = max obs idx, -1 none

__global__ void winner_init_k() {
    int i = blockIdx.x * blockDim.x + threadIdx.x;
    if (i < NEV * B_) g_winner[i] = -1;
}
__global__ void winner_scatter_k(const int* __restrict__ sid) {
    int j = blockIdx.x * blockDim.x + threadIdx.x;
    if (j < TOT_) atomicMax(&g_winner[(j >> 8) * B_ + sid[j]], j);
}

__device__ __forceinline__ float sigm(float x) {
    return __fdividef(1.f, 1.f + __expf(-x));
}
__device__ __forceinline__ float tanh_f(float x) {
    float xc = fminf(fmaxf(x, -15.f), 15.f);
    float e  = __expf(-2.f * xc);
    return __fdividef(1.f - e, 1.f + e);
}

#define FMA2(d, a, b, c) \
    asm("fma.rn.f32x2 %0, %1, %2, %3;" : "=l"(d) : "l"(a), "l"(b), "l"(c))

__device__ __forceinline__ float hadd2(ull v) {
    unsigned lo, hi;
    asm("mov.b64 {%0, %1}, %2;" : "=r"(lo), "=r"(hi) : "l"(v));
    return __uint_as_float(lo) + __uint_as_float(hi);
}
__device__ __forceinline__ float dot8(const float* __restrict__ w, float4 xa, float4 xb) {
    float4 A  = *reinterpret_cast<const float4*>(w);
    float4 Bv = *reinterpret_cast<const float4*>(w + 4);
    float s = A.x * xa.x;
    s = fmaf(A.y,  xa.y, s); s = fmaf(A.z,  xa.z, s); s = fmaf(A.w,  xa.w, s);
    s = fmaf(Bv.x, xb.x, s); s = fmaf(Bv.y, xb.y, s);
    s = fmaf(Bv.z, xb.z, s); s = fmaf(Bv.w, xb.w, s);
    return s;
}

// GRU-Bayes event update for one sample (warp-collective, h in smem).
__device__ __forceinline__ void event_upd(
    float* __restrict__ hs, const float* __restrict__ X, int w,
    const float* __restrict__ sm, 
    const float* pE1, const float* pE2, const float* pE3,
    const float* pE4, const float* pE5, const float* pE6,
    float ebr1, float ebr2, float ebz1, float ebz2,
    float ebi1, float ebi2, float ebh1, float ebh2,
    int lane, int o2)
{
    const float4* xp = reinterpret_cast<const float4*>(X + (size_t)w * 8);
    float4 xa = __ldg(xp), xb = __ldg(xp + 1);
    float gir1 = dot8(sm + OF_WIH + lane*12,       xa, xb);
    float gir2 = dot8(sm + OF_WIH + (32+lane)*12,  xa, xb);
    float giz1 = dot8(sm + OF_WIH + (64+lane)*12,  xa, xb);
    float giz2 = dot8(sm + OF_WIH + (96+lane)*12,  xa, xb);
    float gin1 = dot8(sm + OF_WIH + (128+lane)*12, xa, xb);
    float gin2 = dot8(sm + OF_WIH + (160+lane)*12, xa, xb);
    ull a1=0, a2=0, a3=0, a4=0, a5=0, a6=0;
    const ulonglong2* hp = reinterpret_cast<const ulonglong2*>(hs);
    #pragma unroll
    for (int i = 0; i < 16; i++) {
        ulonglong2 hv = hp[i];
        ulonglong2 w1 = reinterpret_cast<const ulonglong2*>(pE1)[i];
        ulonglong2 w2 = reinterpret_cast<const ulonglong2*>(pE2)[i];
        ulonglong2 w3 = reinterpret_cast<const ulonglong2*>(pE3)[i];
        ulonglong2 w4 = reinterpret_cast<const ulonglong2*>(pE4)[i];
        ulonglong2 w5 = reinterpret_cast<const ulonglong2*>(pE5)[i];
        ulonglong2 w6 = reinterpret_cast<const ulonglong2*>(pE6)[i];
        FMA2(a1, w1.x, hv.x, a1); FMA2(a1, w1.y, hv.y, a1);
        FMA2(a2, w2.x, hv.x, a2); FMA2(a2, w2.y, hv.y, a2);
        FMA2(a3, w3.x, hv.x, a3); FMA2(a3, w3.y, hv.y, a3);
        FMA2(a4, w4.x, hv.x, a4); FMA2(a4, w4.y, hv.y, a4);
        FMA2(a5, w5.x, hv.x, a5); FMA2(a5, w5.y, hv.y, a5);
        FMA2(a6, w6.x, hv.x, a6); FMA2(a6, w6.y, hv.y, a6);
    }
    float h1o = hs[lane], h2o = hs[o2];
    float r1 = sigm(gir1 + hadd2(a1) + ebr1);
    float r2 = sigm(gir2 + hadd2(a2) + ebr2);
    float z1 = sigm(giz1 + hadd2(a3) + ebz1);
    float z2 = sigm(giz2 + hadd2(a4) + ebz2);
    float n1 = tanh_f(gin1 + ebi1 + r1 * (hadd2(a5) + ebh1));
    float n2 = tanh_f(gin2 + ebi2 + r2 * (hadd2(a6) + ebh2));
    float h1n = fmaf(z1, h1o - n1, n1);   // (1-z)*n + z*h
    float h2n = fmaf(z2, h2o - n2, n2);
    __syncwarp();
    hs[lane] = h1n; hs[o2] = h2n;
    __syncwarp();
}

__global__ __launch_bounds__(128, 1)
void ev_gru_main(
    const float* __restrict__ X,
    const float* __restrict__ covs,
    const float* __restrict__ cW1, const float* __restrict__ cb1,
    const float* __restrict__ cW2, const float* __restrict__ cb2,
    const float* __restrict__ gWih, const float* __restrict__ gWhh,
    const float* __restrict__ gbih, const float* __restrict__ gbhh,
    const float* __restrict__ gxb,
    const float* __restrict__ ghrW, const float* __restrict__ ghzW,
    const float* __restrict__ ghhW,
    const float* __restrict__ oW1,  const float* __restrict__ ob1,
    const float* __restrict__ oW2,  const float* __restrict__ ob2,
    float* __restrict__ out)
{
    extern __shared__ float sm[];
    const int tid = threadIdx.x;
    const int blk = blockIdx.x;

    // ---- cooperative weight staging (stride 128) ----
    for (int i = tid; i < 64*64; i += 128) {
        int r = i >> 6, c = i & 63;
        sm[OF_GHR + r*68 + c] = ghrW[i];
        sm[OF_GHZ + r*68 + c] = ghzW[i];
        sm[OF_GHH + r*68 + c] = ghhW[i];
    }
    for (int i = tid; i < 192*64; i += 128) {
        int r = i >> 6, c = i & 63;
        sm[OF_WHH + r*68 + c] = gWhh[i];
    }
    for (int i = tid; i < 128*64; i += 128) {
        int r = i >> 6, c = i & 63;
        sm[OF_W1 + r*68 + c] = oW1[i];
    }
    for (int i = tid; i < 192*8; i += 128) {
        int r = i >> 3, c = i & 7;
        sm[OF_WIH + r*12 + c] = gWih[i];
    }
    for (int i = tid; i < 192; i += 128) {
        sm[OF_BIH + i] = gbih[i];
        sm[OF_BHH + i] = gbhh[i];
        sm[OF_GXB + i] = gxb[i];
    }
    sm[OF_OB1 + tid] = ob1[tid];
    for (int i = tid; i < 256; i += 128) sm[OF_W2 + i] = oW2[i];
    if (tid < 2) sm[OF_OB2 + tid] = ob2[tid];
    __syncthreads();

    const int warp = tid >> 5, lane = tid & 31, o2 = lane + 32;
    const int sA = warp * 2, sB = sA + 1;
    const int bA = blk * 8 + sA, bB = bA + 1;
    float* hA = sm + OF_HS + sA * 64;  float* hB = sm + OF_HS + sB * 64;
    float* rA = sm + OF_RS + sA * 64;  float* rB = sm + OF_RS + sB * 64;

    // ---- h0 = tanh(relu(covs @ cW1^T + cb1) @ cW2^T + cb2), both samples ----
    #pragma unroll
    for (int pick = 0; pick < 2; pick++) {
        const int b = pick ? bB : bA;
        float* hs = pick ? hB : hA;
        float* rs = pick ? rB : rA;
        float t1 = __ldg(cb1 + lane), t2 = __ldg(cb1 + o2);
        #pragma unroll
        for (int k = 0; k < 16; k++) {
            float cv = __ldg(covs + b*16 + k);
            t1 = fmaf(cv, __ldg(cW1 + lane*16 + k), t1);
            t2 = fmaf(cv, __ldg(cW1 + o2*16   + k), t2);
        }
        rs[lane] = fmaxf(t1, 0.f); rs[o2] = fmaxf(t2, 0.f);
        __syncwarp();
        float a1 = __ldg(cb2 + lane), a2 = __ldg(cb2 + o2);
        #pragma unroll 8
        for (int c = 0; c < 64; c++) {
            float tv = rs[c];
            a1 = fmaf(tv, __ldg(cW2 + lane*64 + c), a1);
            a2 = fmaf(tv, __ldg(cW2 + o2*64   + c), a2);
        }
        __syncwarp();
        hs[lane] = tanh_f(a1); hs[o2] = tanh_f(a2);
        __syncwarp();
    }

    // ---- per-lane stationary smem pointers / biases ----
    const float* pR1 = sm + OF_GHR + lane*68; const float* pR2 = pR1 + 32*68;
    const float* pZ1 = sm + OF_GHZ + lane*68; const float* pZ2 = pZ1 + 32*68;
    const float* pU1 = sm + OF_GHH + lane*68; const float* pU2 = pU1 + 32*68;
    const float* pW1a = sm + OF_W1 + lane*68;
    const float* pW1b = pW1a + 32*68;
    const float* pW1c = pW1a + 64*68;
    const float* pW1d = pW1a + 96*68;
    const float* pE1 = sm + OF_WHH + lane*68;
    const float* pE2 = pE1 + 32*68;  const float* pE3 = pE1 + 64*68;
    const float* pE4 = pE1 + 96*68;  const float* pE5 = pE1 + 128*68;
    const float* pE6 = pE1 + 160*68;

    float xr1 = sm[OF_GXB + lane],        xr2 = sm[OF_GXB + o2];
    float xz1 = sm[OF_GXB + 64 + lane],   xz2 = sm[OF_GXB + 64 + o2];
    float xh1 = sm[OF_GXB + 128 + lane],  xh2 = sm[OF_GXB + 128 + o2];
    float ebr1 = sm[OF_BIH + lane]      + sm[OF_BHH + lane];
    float ebr2 = sm[OF_BIH + o2]        + sm[OF_BHH + o2];
    float ebz1 = sm[OF_BIH + 64 + lane] + sm[OF_BHH + 64 + lane];
    float ebz2 = sm[OF_BIH + 64 + o2]   + sm[OF_BHH + 64 + o2];
    float ebi1 = sm[OF_BIH + 128 + lane], ebi2 = sm[OF_BIH + 128 + o2];
    float ebh1 = sm[OF_BHH + 128 + lane], ebh2 = sm[OF_BHH + 128 + o2];
    float hb0 = sm[OF_OB1 + lane],      hb1 = sm[OF_OB1 + lane + 32];
    float hb2 = sm[OF_OB1 + lane + 64], hb3 = sm[OF_OB1 + lane + 96];
    float w200 = sm[OF_W2 + lane],       w201 = sm[OF_W2 + lane + 32];
    float w202 = sm[OF_W2 + lane + 64],  w203 = sm[OF_W2 + lane + 96];
    float w210 = sm[OF_W2 + 128 + lane],      w211 = sm[OF_W2 + 128 + lane + 32];
    float w212 = sm[OF_W2 + 128 + lane + 64], w213 = sm[OF_W2 + 128 + lane + 96];
    float b20 = sm[OF_OB2], b21 = sm[OF_OB2 + 1];

    // ================= main time loop (warp-independent) =================
    for (int t = 0; ; t++) {
        // ---- events (last-dup wins; computed from pre-update h) ----
        if (t < NEV) {
            int wA = g_winner[t * B_ + bA];
            int wB = g_winner[t * B_ + bB];
            if (wA >= 0)
                event_upd(hA, X, wA, sm, pE1,pE2,pE3,pE4,pE5,pE6,
                          ebr1,ebr2,ebz1,ebz2,ebi1,ebi2,ebh1,ebh2, lane, o2);
            if (wB >= 0)
                event_upd(hB, X, wB, sm, pE1,pE2,pE3,pE4,pE5,pE6,
                          ebr1,ebr2,ebz1,ebz2,ebi1,ebi2,ebh1,ebh2, lane, o2);
        }

        // ---- PASS1: 8 weight rows shared across both samples ----
        ull ac[16];
        #pragma unroll
        for (int i = 0; i < 16; i++) ac[i] = 0;
        {
            const ulonglong2* hpA = reinterpret_cast<const ulonglong2*>(hA);
            const ulonglong2* hpB = reinterpret_cast<const ulonglong2*>(hB);
            #pragma unroll
            for (int i = 0; i < 16; i++) {
                ulonglong2 hvA = hpA[i], hvB = hpB[i];
                ulonglong2 w;
                w = reinterpret_cast<const ulonglong2*>(pR1)[i];
                FMA2(ac[0], w.x, hvA.x, ac[0]); FMA2(ac[0], w.y, hvA.y, ac[0]);
                FMA2(ac[1], w.x, hvB.x, ac[1]); FMA2(ac[1], w.y, hvB.y, ac[1]);
                w = reinterpret_cast<const ulonglong2*>(pR2)[i];
                FMA2(ac[2], w.x, hvA.x, ac[2]); FMA2(ac[2], w.y, hvA.y, ac[2]);
                FMA2(ac[3], w.x, hvB.x, ac[3]); FMA2(ac[3], w.y, hvB.y, ac[3]);
                w = reinterpret_cast<const ulonglong2*>(pZ1)[i];
                FMA2(ac[4], w.x, hvA.x, ac[4]); FMA2(ac[4], w.y, hvA.y, ac[4]);
                FMA2(ac[5], w.x, hvB.x, ac[5]); FMA2(ac[5], w.y, hvB.y, ac[5]);
                w = reinterpret_cast<const ulonglong2*>(pZ2)[i];
                FMA2(ac[6], w.x, hvA.x, ac[6]); FMA2(ac[6], w.y, hvA.y, ac[6]);
                FMA2(ac[7], w.x, hvB.x, ac[7]); FMA2(ac[7], w.y, hvB.y, ac[7]);
                w = reinterpret_cast<const ulonglong2*>(pW1a)[i];
                FMA2(ac[8],  w.x, hvA.x, ac[8]);  FMA2(ac[8],  w.y, hvA.y, ac[8]);
                FMA2(ac[9],  w.x, hvB.x, ac[9]);  FMA2(ac[9],  w.y, hvB.y, ac[9]);
                w = reinterpret_cast<const ulonglong2*>(pW1b)[i];
                FMA2(ac[10], w.x, hvA.x, ac[10]); FMA2(ac[10], w.y, hvA.y, ac[10]);
                FMA2(ac[11], w.x, hvB.x, ac[11]); FMA2(ac[11], w.y, hvB.y, ac[11]);
                w = reinterpret_cast<const ulonglong2*>(pW1c)[i];
                FMA2(ac[12], w.x, hvA.x, ac[12]); FMA2(ac[12], w.y, hvA.y, ac[12]);
                FMA2(ac[13], w.x, hvB.x, ac[13]); FMA2(ac[13], w.y, hvB.y, ac[13]);
                w = reinterpret_cast<const ulonglong2*>(pW1d)[i];
                FMA2(ac[14], w.x, hvA.x, ac[14]); FMA2(ac[14], w.y, hvA.y, ac[14]);
                FMA2(ac[15], w.x, hvB.x, ac[15]); FMA2(ac[15], w.y, hvB.y, ac[15]);
            }
        }
        // ---- epilogue pass1 + head, per sample ----
        float zA1, zA2, zB1, zB2;
        {
            float h1 = hA[lane], h2 = hA[o2];
            float r1 = sigm(hadd2(ac[0]) + xr1), r2 = sigm(hadd2(ac[2]) + xr2);
            zA1 = sigm(hadd2(ac[4]) + xz1);      zA2 = sigm(hadd2(ac[6]) + xz2);
            float d0 = fmaxf(hadd2(ac[8])  + hb0, 0.f);
            float d1 = fmaxf(hadd2(ac[10]) + hb1, 0.f);
            float d2 = fmaxf(hadd2(ac[12]) + hb2, 0.f);
            float d3 = fmaxf(hadd2(ac[14]) + hb3, 0.f);
            float p0 = d0*w200; p0 = fmaf(d1,w201,p0); p0 = fmaf(d2,w202,p0); p0 = fmaf(d3,w203,p0);
            float p1 = d0*w210; p1 = fmaf(d1,w211,p1); p1 = fmaf(d2,w212,p1); p1 = fmaf(d3,w213,p1);
            #pragma unroll
            for (int s = 16; s > 0; s >>= 1) {
                p0 += __shfl_xor_sync(0xffffffffu, p0, s);
                p1 += __shfl_xor_sync(0xffffffffu, p1, s);
            }
            __syncwarp();
            rA[lane] = r1 * h1; rA[o2] = r2 * h2;
            if (lane == 0) {
                float* orow = out + (size_t)t * (B_*2) + bA*2;
                orow[0] = p0 + b20; orow[1] = p1 + b21;
            }
        }
        {
            float h1 = hB[lane], h2 = hB[o2];
            float r1 = sigm(hadd2(ac[1]) + xr1), r2 = sigm(hadd2(ac[3]) + xr2);
            zB1 = sigm(hadd2(ac[5]) + xz1);      zB2 = sigm(hadd2(ac[7]) + xz2);
            float d0 = fmaxf(hadd2(ac[9])  + hb0, 0.f);
            float d1 = fmaxf(hadd2(ac[11]) + hb1, 0.f);
            float d2 = fmaxf(hadd2(ac[13]) + hb2, 0.f);
            float d3 = fmaxf(hadd2(ac[15]) + hb3, 0.f);
            float p0 = d0*w200; p0 = fmaf(d1,w201,p0); p0 = fmaf(d2,w202,p0); p0 = fmaf(d3,w203,p0);
            float p1 = d0*w210; p1 = fmaf(d1,w211,p1); p1 = fmaf(d2,w212,p1); p1 = fmaf(d3,w213,p1);
            #pragma unroll
            for (int s = 16; s > 0; s >>= 1) {
                p0 += __shfl_xor_sync(0xffffffffu, p0, s);
                p1 += __shfl_xor_sync(0xffffffffu, p1, s);
            }
            __syncwarp();
            rB[lane] = r1 * h1; rB[o2] = r2 * h2;
            if (lane == 0) {
                float* orow = out + (size_t)t * (B_*2) + bB*2;
                orow[0] = p0 + b20; orow[1] = p1 + b21;
            }
        }
        if (t == NSTEPS) break;
        __syncwarp();

        // ---- PASS2: ghh on (r*h), 2 rows shared across both samples ----
        ull u0=0, u1=0, u2=0, u3=0;
        {
            const ulonglong2* rpA = reinterpret_cast<const ulonglong2*>(rA);
            const ulonglong2* rpB = reinterpret_cast<const ulonglong2*>(rB);
            #pragma unroll
            for (int i = 0; i < 16; i++) {
                ulonglong2 rvA = rpA[i], rvB = rpB[i];
                ulonglong2 w;
                w = reinterpret_cast<const ulonglong2*>(pU1)[i];
                FMA2(u0, w.x, rvA.x, u0); FMA2(u0, w.y, rvA.y, u0);
                FMA2(u1, w.x, rvB.x, u1); FMA2(u1, w.y, rvB.y, u1);
                w = reinterpret_cast<const ulonglong2*>(pU2)[i];
                FMA2(u2, w.x, rvA.x, u2); FMA2(u2, w.y, rvA.y, u2);
                FMA2(u3, w.x, rvB.x, u3); FMA2(u3, w.y, rvB.y, u3);
            }
        }
        // ---- Euler updates ----
        {
            float h1 = hA[lane], h2 = hA[o2];
            float uu1 = tanh_f(xh1 + hadd2(u0));
            float uu2 = tanh_f(xh2 + hadd2(u2));
            float h1n = fmaf(DT_ * (1.f - zA1), uu1 - h1, h1);
            float h2n = fmaf(DT_ * (1.f - zA2), uu2 - h2, h2);
            float h3 = hB[lane], h4 = hB[o2];
            float uu3 = tanh_f(xh1 + hadd2(u1));
            float uu4 = tanh_f(xh2 + hadd2(u3));
            float h3n = fmaf(DT_ * (1.f - zB1), uu3 - h3, h3);
            float h4n = fmaf(DT_ * (1.f - zB2), uu4 - h4, h4);
            __syncwarp();
            hA[lane] = h1n; hA[o2] = h2n;
            hB[lane] = h3n; hB[o2] = h4n;
            __syncwarp();
        }
    }
}

extern "C" void kernel_launch(void* const* d_in, const int* in_sizes, int n_in,
                              void* d_out, int out_size)
{
    (void)in_sizes; (void)n_in; (void)out_size;
    const float* X    = (const float*)d_in[2];
    const int*   sid  = (const int*)  d_in[3];
    const float* covs = (const float*)d_in[4];
    const float* cW1  = (const float*)d_in[6];
    const float* cb1  = (const float*)d_in[7];
    const float* cW2  = (const float*)d_in[8];
    const float* cb2  = (const float*)d_in[9];
    const float* gWih = (const float*)d_in[10];
    const float* gWhh = (const float*)d_in[11];
    const float* gbih = (const float*)d_in[12];
    const float* gbhh = (const float*)d_in[13];
    const float* gxb  = (const float*)d_in[15];
    const float* ghrW = (const float*)d_in[16];
    const float* ghzW = (const float*)d_in[17];
    const float* ghhW = (const float*)d_in[18];
    const float* oW1  = (const float*)d_in[19];
    const float* ob1  = (const float*)d_in[20];
    const float* oW2  = (const float*)d_in[21];
    const float* ob2  = (const float*)d_in[22];
    float* out = (float*)d_out;

    winner_init_k<<<(NEV * B_ + 255) / 256, 256>>>();
    winner_scatter_k<<<(TOT_ + 255) / 256, 256>>>(sid);

    size_t smem = SMEM_FLOATS * sizeof(float);
    cudaFuncSetAttribute(ev_gru_main, cudaFuncAttributeMaxDynamicSharedMemorySize, (int)smem);
    ev_gru_main<<<B_ / 8, 128, smem>>>(X, covs, cW1, cb1, cW2, cb2,
                                       gWih, gWhh, gbih, gbhh, gxb,
                                       ghrW, ghzW, ghhW, oW1, ob1, oW2, ob2, out);
}